// round 10
// baseline (speedup 1.0000x reference)
#include <cuda_runtime.h>
#include <cstdint>
#include <math.h>
#include <mma.h>
#include <cuda_fp16.h>

using namespace nvcuda;

#define B_    2
#define T_    2048
#define C_    2048
#define HQ_   16
#define HKV_  4
#define DH_   128
#define WIN_  512
#define NQKV_ 3072          // (HQ + 2*HKV) * DH
#define MTOK_ 4096          // B * T

// ---------------- scratch (static __device__, no allocations) ----------------
__device__ float  g_qkv[MTOK_ * NQKV_];            // fp32 qkv (pre-rope)
__device__ __half g_Qh[B_ * HQ_ * T_ * DH_];       // fp16, pre-scaled by 1/sqrt(d)
__device__ __half g_Kh[B_ * HKV_ * T_ * DH_];
__device__ __half g_Vh[B_ * HKV_ * T_ * DH_];
__device__ __half g_yh[MTOK_ * C_];                // fp16 attention output
__device__ __half g_xh[MTOK_ * C_];                // fp16 x
__device__ __half g_wqh[NQKV_ * C_];               // fp16 w_qkv
__device__ __half g_wph[C_ * C_];                  // fp16 w_proj

// ============================================================================
// fp32 -> fp16 (RNE) conversion
// ============================================================================
__global__ __launch_bounds__(256) void to_half(
    const float* __restrict__ in, __half* __restrict__ out, int n4)
{
    const int i = blockIdx.x * blockDim.x + threadIdx.x;
    if (i >= n4) return;
    float4 v = ((const float4*)in)[i];
    __half2* o = (__half2*)out;
    o[2 * i]     = __floats2half2_rn(v.x, v.y);
    o[2 * i + 1] = __floats2half2_rn(v.z, v.w);
}

// ============================================================================
// FP16 tensor-core GEMM:  C[M,N] = A[M,K] @ B[N,K]^T  (row-major, K contig)
// CTA tile 128x128, BK=64 (halves barrier frequency per K-elem vs BK=32),
// 3-stage cp.async, 8 warps 2(m) x 4(n), warp tile 64x32, fp32 accumulate,
// 2 CTAs/SM via __launch_bounds__(256,2).
// ============================================================================
#define BM_   128
#define BN_   128
#define GBK_  64
#define GLD_  72          // halfs per row (64 + 8 pad); 144B, 16B-multiple
#define GS_   3
#define GEMM_SMEM (GS_ * (BM_ + BN_) * GLD_ * (int)sizeof(__half))

__device__ __forceinline__ void cp_async16(void* smem_dst, const void* gsrc) {
    unsigned int d = (unsigned int)__cvta_generic_to_shared(smem_dst);
    asm volatile("cp.async.cg.shared.global [%0], [%1], 16;\n" :: "r"(d), "l"(gsrc));
}

__global__ __launch_bounds__(256, 2) void gemm_fp16(
    const __half* __restrict__ A, const __half* __restrict__ Bm,
    float* __restrict__ Cm, int M, int N, int K)
{
    extern __shared__ __align__(16) __half hsm[];
    __half (*As)[BM_][GLD_] = (__half (*)[BM_][GLD_])hsm;
    __half (*Bs)[BN_][GLD_] = (__half (*)[BN_][GLD_])(hsm + GS_ * BM_ * GLD_);

    const int tid = threadIdx.x;
    const int wid = tid >> 5;
    const int m0  = blockIdx.y * BM_;
    const int n0  = blockIdx.x * BN_;
    const int wm  = (wid & 1) * 64;     // 2 warps over 128 m
    const int wn  = (wid >> 1) * 32;    // 4 warps over 128 n

    // load mapping: 64 halfs/row = 8 x 8-half chunks; thread does cols lc,lc+32
    const int lr = tid >> 2;            // 0..63
    const int lc = (tid & 3) << 3;      // 0,8,16,24

    const __half* Abase = A  + (size_t)(m0 + lr) * K + lc;
    const __half* Bbase = Bm + (size_t)(n0 + lr) * K + lc;
    const size_t rowK64 = (size_t)64 * K;

    wmma::fragment<wmma::accumulator, 16, 16, 16, float> acc[4][2];
#pragma unroll
    for (int i = 0; i < 4; i++)
#pragma unroll
        for (int j = 0; j < 2; j++)
            wmma::fill_fragment(acc[i][j], 0.0f);

    const int KT = K / GBK_;

#pragma unroll
    for (int s = 0; s < GS_ - 1; ++s) {
        const size_t ko = (size_t)s * GBK_;
        cp_async16(&As[s][lr][lc],           Abase + ko);
        cp_async16(&As[s][lr][lc + 32],      Abase + ko + 32);
        cp_async16(&As[s][lr + 64][lc],      Abase + ko + rowK64);
        cp_async16(&As[s][lr + 64][lc + 32], Abase + ko + rowK64 + 32);
        cp_async16(&Bs[s][lr][lc],           Bbase + ko);
        cp_async16(&Bs[s][lr][lc + 32],      Bbase + ko + 32);
        cp_async16(&Bs[s][lr + 64][lc],      Bbase + ko + rowK64);
        cp_async16(&Bs[s][lr + 64][lc + 32], Bbase + ko + rowK64 + 32);
        asm volatile("cp.async.commit_group;\n" ::);
    }

    for (int kt = 0; kt < KT; ++kt) {
        asm volatile("cp.async.wait_group %0;\n" :: "n"(GS_ - 2));
        __syncthreads();

        if (kt + GS_ - 1 < KT) {
            const int ws = (kt + GS_ - 1) % GS_;
            const size_t ko = (size_t)(kt + GS_ - 1) * GBK_;
            cp_async16(&As[ws][lr][lc],           Abase + ko);
            cp_async16(&As[ws][lr][lc + 32],      Abase + ko + 32);
            cp_async16(&As[ws][lr + 64][lc],      Abase + ko + rowK64);
            cp_async16(&As[ws][lr + 64][lc + 32], Abase + ko + rowK64 + 32);
            cp_async16(&Bs[ws][lr][lc],           Bbase + ko);
            cp_async16(&Bs[ws][lr][lc + 32],      Bbase + ko + 32);
            cp_async16(&Bs[ws][lr + 64][lc],      Bbase + ko + rowK64);
            cp_async16(&Bs[ws][lr + 64][lc + 32], Bbase + ko + rowK64 + 32);
        }
        asm volatile("cp.async.commit_group;\n" ::);

        const int st = kt % GS_;
#pragma unroll
        for (int ks = 0; ks < 4; ++ks) {
            wmma::fragment<wmma::matrix_a, 16, 16, 16, half, wmma::row_major> af[4];
            wmma::fragment<wmma::matrix_b, 16, 16, 16, half, wmma::col_major> bf[2];
#pragma unroll
            for (int i = 0; i < 4; i++)
                wmma::load_matrix_sync(af[i], &As[st][wm + i * 16][ks * 16], GLD_);
#pragma unroll
            for (int j = 0; j < 2; j++)
                wmma::load_matrix_sync(bf[j], &Bs[st][wn + j * 16][ks * 16], GLD_);
#pragma unroll
            for (int i = 0; i < 4; i++)
#pragma unroll
                for (int j = 0; j < 2; j++)
                    wmma::mma_sync(acc[i][j], af[i], bf[j], acc[i][j]);
        }
    }

#pragma unroll
    for (int i = 0; i < 4; i++)
#pragma unroll
        for (int j = 0; j < 2; j++)
            wmma::store_matrix_sync(
                Cm + (size_t)(m0 + wm + i * 16) * N + (n0 + wn + j * 16),
                acc[i][j], N, wmma::mem_row_major);
}

// ============================================================================
// RoPE + RMSNorm + head split; 4 heads per 256-thread block (one uniform
// __syncthreads; no early returns).  Q pre-scaled by 1/sqrt(d), fp16 out.
// ============================================================================
__global__ __launch_bounds__(256) void rope_rms(
    const float* __restrict__ qkv,
    __half* __restrict__ Qo, __half* __restrict__ Ko, __half* __restrict__ Vo)
{
    const int tid  = threadIdx.x;
    const int unit = tid >> 6;                 // 0..3
    const int i    = tid & 63;                 // pair index within head
    const int h    = blockIdx.x * 4 + unit;    // 0..23
    const int t    = blockIdx.y;
    const int b    = blockIdx.z;

    const float* src = qkv + ((size_t)(b * T_ + t)) * NQKV_ + h * DH_;
    const float x0 = src[2 * i];
    const float x1 = src[2 * i + 1];

    const bool isV = (h >= HQ_ + HKV_);

    // RoPE (computed for all; unused for V)
    const float inv_freq = powf(10000.0f, -(float)i * (1.0f / 64.0f));
    const float ang = (float)t * inv_freq;
    float sn, cs;
    sincosf(ang, &sn, &cs);
    const float y0 = x0 * cs - x1 * sn;
    const float y1 = x1 * cs + x0 * sn;

    // per-head RMS reduce: warp reduce + combine the unit's 2 warps
    float ss = y0 * y0 + y1 * y1;
#pragma unroll
    for (int off = 16; off; off >>= 1)
        ss += __shfl_xor_sync(0xffffffffu, ss, off);
    __shared__ float sh[8];
    if ((tid & 31) == 0) sh[tid >> 5] = ss;
    __syncthreads();
    float rn = rsqrtf((sh[unit * 2] + sh[unit * 2 + 1]) * (1.0f / 128.0f)
                      + 1.1920929e-07f);

    if (isV) {
        __half2* dst = (__half2*)(Vo +
            ((size_t)(b * HKV_ + (h - HQ_ - HKV_)) * T_ + t) * DH_);
        dst[i] = __floats2half2_rn(x0, x1);
    } else if (h < HQ_) {
        rn *= 0.08838834764831845f;            // fold 1/sqrt(128) into Q
        __half2* dst = (__half2*)(Qo + ((size_t)(b * HQ_ + h) * T_ + t) * DH_);
        dst[i] = __floats2half2_rn(y0 * rn, y1 * rn);
    } else {
        __half2* dst = (__half2*)(Ko + ((size_t)(b * HKV_ + (h - HQ_)) * T_ + t) * DH_);
        dst[i] = __floats2half2_rn(y0 * rn, y1 * rn);
    }
}

// ============================================================================
// Sliding-window flash attention, fp16 wmma, fp32 accumulate.
// Tile 128q x 64k, DH=128, 256 threads = 8 warps.
//   S:  warps 4(m) x 2(n), warp tile 32q x 32k.
//   softmax: SIMT, thread = 8 rows x 4 cols.
//   PV: warps 4(m) x 2(n), warp tile 32q x 64d, staged via shared fp32 buf.
// S staging and O staging share one fp32 buffer (disjoint phases).
// ============================================================================
#define AQT_ 128            // q rows per block
#define QL_  136            // half ld for Q/K/V tiles (128 + 8)
#define PL_  72             // half ld for P tile (64 + 8)
#define OL_  132            // float ld for S/O staging (128 + 4)
#define ATTN_SMEM (AQT_ * OL_ * (int)sizeof(float) + \
                   ((AQT_ + 2 * 64) * QL_ + AQT_ * PL_) * (int)sizeof(__half))

__global__ __launch_bounds__(256, 1) void attn_tc(
    const __half* __restrict__ Qg, const __half* __restrict__ Kg,
    const __half* __restrict__ Vg, __half* __restrict__ Yg)
{
    extern __shared__ __align__(16) char asm_[];
    float*  Osf = (float*)asm_;                       // 128 x 132 fp32 (S & O)
    __half* Qsh = (__half*)(Osf + AQT_ * OL_);        // 128 x 136
    __half* Ksh = Qsh + AQT_ * QL_;                   // 64 x 136
    __half* Vsh = Ksh + 64 * QL_;                     // 64 x 136
    __half* Psh = Vsh + 64 * QL_;                     // 128 x 72

    const int tid = threadIdx.x;
    const int tx  = tid & 15;
    const int ty  = tid >> 4;
    const int wid = tid >> 5;
    const int q0  = blockIdx.x * AQT_;
    const int h   = blockIdx.y;
    const int b   = blockIdx.z;
    const int hk  = h >> 2;

    const __half* Qp = Qg + ((size_t)(b * HQ_ + h) * T_ + q0) * DH_;
    const __half* Kp = Kg + ((size_t)(b * HKV_ + hk) * T_) * DH_;
    const __half* Vp = Vg + ((size_t)(b * HKV_ + hk) * T_) * DH_;

    // Q tile: pure 16B copies (Q already scaled + fp16); 128 rows x 16 chunks
    for (int li = tid; li < AQT_ * 16; li += 256) {
        const int r  = li >> 4;
        const int c8 = (li & 15) << 3;
        *(uint4*)(Qsh + r * QL_ + c8) = *(const uint4*)(Qp + (size_t)r * DH_ + c8);
    }

    float m_i[8], l_i[8], acc[8][8];
#pragma unroll
    for (int i = 0; i < 8; i++) {
        m_i[i] = -1e30f; l_i[i] = 0.f;
#pragma unroll
        for (int j = 0; j < 8; j++) acc[i][j] = 0.f;
    }

    int lo = q0 - (WIN_ - 1); if (lo < 0) lo = 0;
    const int kt0 = lo >> 6;
    const int kt1 = (q0 + AQT_ - 1) >> 6;

    for (int kt = kt0; kt <= kt1; ++kt) {
        const int k0 = kt << 6;

        // ---- load K, V tiles (16B copies), 64 rows x 16 chunks each ----
        for (int li = tid; li < 64 * 16; li += 256) {
            const int r  = li >> 4;
            const int c8 = (li & 15) << 3;
            *(uint4*)(Ksh + r * QL_ + c8) =
                *(const uint4*)(Kp + (size_t)(k0 + r) * DH_ + c8);
            *(uint4*)(Vsh + r * QL_ + c8) =
                *(const uint4*)(Vp + (size_t)(k0 + r) * DH_ + c8);
        }
        __syncthreads();

        // ---- S = Q K^T: warp (wy, wx) does 32q x 32k -> Osf ----
        {
            const int wy = (wid & 3) * 32;
            const int wx = (wid >> 2) * 32;
            wmma::fragment<wmma::accumulator, 16, 16, 16, float> sacc[2][2];
#pragma unroll
            for (int i = 0; i < 2; i++)
#pragma unroll
                for (int j = 0; j < 2; j++)
                    wmma::fill_fragment(sacc[i][j], 0.0f);
#pragma unroll
            for (int d = 0; d < DH_; d += 16) {
                wmma::fragment<wmma::matrix_a, 16, 16, 16, half, wmma::row_major> af[2];
                wmma::fragment<wmma::matrix_b, 16, 16, 16, half, wmma::col_major> bf[2];
                wmma::load_matrix_sync(af[0], Qsh + (wy + 0)  * QL_ + d, QL_);
                wmma::load_matrix_sync(af[1], Qsh + (wy + 16) * QL_ + d, QL_);
                wmma::load_matrix_sync(bf[0], Ksh + (wx + 0)  * QL_ + d, QL_);
                wmma::load_matrix_sync(bf[1], Ksh + (wx + 16) * QL_ + d, QL_);
#pragma unroll
                for (int i = 0; i < 2; i++)
#pragma unroll
                    for (int j = 0; j < 2; j++)
                        wmma::mma_sync(sacc[i][j], af[i], bf[j], sacc[i][j]);
            }
#pragma unroll
            for (int i = 0; i < 2; i++)
#pragma unroll
                for (int j = 0; j < 2; j++)
                    wmma::store_matrix_sync(
                        Osf + (wy + i * 16) * OL_ + wx + j * 16,
                        sacc[i][j], OL_, wmma::mem_row_major);
        }
        __syncthreads();

        // ---- softmax (SIMT): 8 rows x 4 cols per thread ----
#pragma unroll
        for (int i = 0; i < 8; i++) {
            const int row = ty * 8 + i;
            const int qi  = q0 + row;
            const float* srow = Osf + row * OL_ + (tx << 2);
            float s0 = srow[0], s1 = srow[1], s2 = srow[2], s3 = srow[3];
            const int kj = k0 + (tx << 2);
            s0 = (qi >= kj + 0 && (qi - kj - 0) < WIN_) ? s0 : -1e30f;
            s1 = (qi >= kj + 1 && (qi - kj - 1) < WIN_) ? s1 : -1e30f;
            s2 = (qi >= kj + 2 && (qi - kj - 2) < WIN_) ? s2 : -1e30f;
            s3 = (qi >= kj + 3 && (qi - kj - 3) < WIN_) ? s3 : -1e30f;
            float rmax = fmaxf(fmaxf(s0, s1), fmaxf(s2, s3));
#pragma unroll
            for (int off = 8; off; off >>= 1)
                rmax = fmaxf(rmax, __shfl_xor_sync(0xffffffffu, rmax, off));
            const float mn = fmaxf(m_i[i], rmax);

            float p0 = __expf(s0 - mn), p1 = __expf(s1 - mn);
            float p2 = __expf(s2 - mn), p3 = __expf(s3 - mn);
            float rs = p0 + p1 + p2 + p3;
#pragma unroll
            for (int off = 8; off; off >>= 1)
                rs += __shfl_xor_sync(0xffffffffu, rs, off);

            const float sc = __expf(m_i[i] - mn);
            l_i[i] = l_i[i] * sc + rs;
            m_i[i] = mn;
#pragma unroll
            for (int j = 0; j < 8; j++) acc[i][j] *= sc;

            __half2* prow = (__half2*)(Psh + row * PL_ + (tx << 2));
            prow[0] = __floats2half2_rn(p0, p1);
            prow[1] = __floats2half2_rn(p2, p3);
        }
        __syncthreads();

        // ---- O_tile = P V: warp (wm, wn) does 32q x 64d -> Osf ----
        {
            const int wm = (wid & 3) * 32;
            const int wn = (wid >> 2) * 64;
            wmma::fragment<wmma::accumulator, 16, 16, 16, float> oacc[2][4];
#pragma unroll
            for (int i = 0; i < 2; i++)
#pragma unroll
                for (int j = 0; j < 4; j++)
                    wmma::fill_fragment(oacc[i][j], 0.0f);
#pragma unroll
            for (int k = 0; k < 64; k += 16) {
                wmma::fragment<wmma::matrix_a, 16, 16, 16, half, wmma::row_major> af[2];
                wmma::fragment<wmma::matrix_b, 16, 16, 16, half, wmma::row_major> bf[4];
                wmma::load_matrix_sync(af[0], Psh + (wm + 0)  * PL_ + k, PL_);
                wmma::load_matrix_sync(af[1], Psh + (wm + 16) * PL_ + k, PL_);
#pragma unroll
                for (int j = 0; j < 4; j++)
                    wmma::load_matrix_sync(bf[j], Vsh + k * QL_ + wn + j * 16, QL_);
#pragma unroll
                for (int i = 0; i < 2; i++)
#pragma unroll
                    for (int j = 0; j < 4; j++)
                        wmma::mma_sync(oacc[i][j], af[i], bf[j], oacc[i][j]);
            }
#pragma unroll
            for (int i = 0; i < 2; i++)
#pragma unroll
                for (int j = 0; j < 4; j++)
                    wmma::store_matrix_sync(
                        Osf + (wm + i * 16) * OL_ + wn + j * 16,
                        oacc[i][j], OL_, wmma::mem_row_major);
        }
        __syncthreads();

        // ---- merge staged O tile into SIMT accumulators ----
#pragma unroll
        for (int i = 0; i < 8; i++) {
            const float* orow = Osf + (ty * 8 + i) * OL_ + (tx << 3);
#pragma unroll
            for (int j = 0; j < 8; j++) acc[i][j] += orow[j];
        }
        __syncthreads();   // Osf/Ksh/Vsh rewritten next iteration
    }

    // epilogue: y = acc / l, fp16 (feeds the proj GEMM directly)
#pragma unroll
    for (int i = 0; i < 8; i++) {
        const float inv = 1.0f / l_i[i];
        const int t = q0 + ty * 8 + i;
        __half2 o[4];
#pragma unroll
        for (int j = 0; j < 4; j++)
            o[j] = __floats2half2_rn(acc[i][2 * j] * inv, acc[i][2 * j + 1] * inv);
        *(uint4*)(Yg + ((size_t)(b * T_ + t)) * C_ + h * DH_ + (tx << 3)) =
            *(uint4*)o;
    }
}

// ============================================================================
// launch
// ============================================================================
extern "C" void kernel_launch(void* const* d_in, const int* in_sizes, int n_in,
                              void* d_out, int out_size)
{
    const float* x      = (const float*)d_in[0];
    const float* w_qkv  = (const float*)d_in[1];
    const float* w_proj = (const float*)d_in[2];
    float* out = (float*)d_out;

    float *p_qkv;
    __half *p_Qh, *p_Kh, *p_Vh, *p_yh, *p_xh, *p_wqh, *p_wph;
    cudaGetSymbolAddress((void**)&p_qkv, g_qkv);
    cudaGetSymbolAddress((void**)&p_Qh,  g_Qh);
    cudaGetSymbolAddress((void**)&p_Kh,  g_Kh);
    cudaGetSymbolAddress((void**)&p_Vh,  g_Vh);
    cudaGetSymbolAddress((void**)&p_yh,  g_yh);
    cudaGetSymbolAddress((void**)&p_xh,  g_xh);
    cudaGetSymbolAddress((void**)&p_wqh, g_wqh);
    cudaGetSymbolAddress((void**)&p_wph, g_wph);

    cudaFuncSetAttribute(gemm_fp16, cudaFuncAttributeMaxDynamicSharedMemorySize, GEMM_SMEM);
    cudaFuncSetAttribute(attn_tc, cudaFuncAttributeMaxDynamicSharedMemorySize, ATTN_SMEM);

    // 0) convert GEMM inputs to fp16 (RNE)
    to_half<<<(MTOK_ * C_ / 4 + 255) / 256, 256>>>(x, p_xh, MTOK_ * C_ / 4);
    to_half<<<(NQKV_ * C_ / 4 + 255) / 256, 256>>>(w_qkv, p_wqh, NQKV_ * C_ / 4);
    to_half<<<(C_ * C_ / 4 + 255) / 256, 256>>>(w_proj, p_wph, C_ * C_ / 4);

    // 1) qkv = x @ w_qkv^T   (fp16 HMMA, fp32 accum, 2 CTAs/SM, BK=64)
    gemm_fp16<<<dim3(NQKV_ / BN_, MTOK_ / BM_), 256, GEMM_SMEM>>>(
        p_xh, p_wqh, p_qkv, MTOK_, NQKV_, C_);

    // 2) RoPE + RMSNorm + split; 4 heads per block
    rope_rms<<<dim3((HQ_ + 2 * HKV_) / 4, T_, B_), 256>>>(p_qkv, p_Qh, p_Kh, p_Vh);

    // 3) attention (fp16 tensor cores, 128q tiles); y written fp16
    attn_tc<<<dim3(T_ / AQT_, HQ_, B_), 256, ATTN_SMEM>>>(p_Qh, p_Kh, p_Vh, p_yh);

    // 4) out = y @ w_proj^T  (fp16 HMMA, fp32 accum, 2 CTAs/SM, BK=64)
    gemm_fp16<<<dim3(C_ / BN_, MTOK_ / BM_), 256, GEMM_SMEM>>>(
        p_yh, p_wph, out, MTOK_, C_, C_);
}

// round 11
// speedup vs baseline: 1.1427x; 1.1427x over previous
#include <cuda_runtime.h>
#include <cstdint>
#include <math.h>
#include <mma.h>
#include <cuda_fp16.h>

using namespace nvcuda;

#define B_    2
#define T_    2048
#define C_    2048
#define HQ_   16
#define HKV_  4
#define DH_   128
#define WIN_  512
#define NQKV_ 3072          // (HQ + 2*HKV) * DH
#define MTOK_ 4096          // B * T

// ---------------- scratch (static __device__, no allocations) ----------------
__device__ float  g_qkv[MTOK_ * NQKV_];            // fp32 qkv (pre-rope)
__device__ __half g_Qh[B_ * HQ_ * T_ * DH_];       // fp16, pre-scaled by 1/sqrt(d)
__device__ __half g_Kh[B_ * HKV_ * T_ * DH_];
__device__ __half g_Vh[B_ * HKV_ * T_ * DH_];
__device__ __half g_yh[MTOK_ * C_];                // fp16 attention output
__device__ __half g_xh[MTOK_ * C_];                // fp16 x
__device__ __half g_wqh[NQKV_ * C_];               // fp16 w_qkv
__device__ __half g_wph[C_ * C_];                  // fp16 w_proj

// ============================================================================
// fp32 -> fp16 (RNE) conversion
// ============================================================================
__global__ __launch_bounds__(256) void to_half(
    const float* __restrict__ in, __half* __restrict__ out, int n4)
{
    const int i = blockIdx.x * blockDim.x + threadIdx.x;
    if (i >= n4) return;
    float4 v = ((const float4*)in)[i];
    __half2* o = (__half2*)out;
    o[2 * i]     = __floats2half2_rn(v.x, v.y);
    o[2 * i + 1] = __floats2half2_rn(v.z, v.w);
}

// ============================================================================
// FP16 tensor-core GEMM (exact R8/R9 winning config):  C = A @ B^T.
// CTA tile 128x128, BK=32, 3-stage cp.async, 8 warps 2(m) x 4(n),
// warp tile 64x32, fp32 accumulate, 2 CTAs/SM.
// ============================================================================
#define BM_   128
#define BN_   128
#define GBK_  32
#define GLD_  40          // halfs per row (32 + 8 pad); 80B, 16B-multiple
#define GS_   3
#define GEMM_SMEM (GS_ * (BM_ + BN_) * GLD_ * (int)sizeof(__half))

__device__ __forceinline__ void cp_async16(void* smem_dst, const void* gsrc) {
    unsigned int d = (unsigned int)__cvta_generic_to_shared(smem_dst);
    asm volatile("cp.async.cg.shared.global [%0], [%1], 16;\n" :: "r"(d), "l"(gsrc));
}

__global__ __launch_bounds__(256, 2) void gemm_fp16(
    const __half* __restrict__ A, const __half* __restrict__ Bm,
    float* __restrict__ Cm, int M, int N, int K)
{
    extern __shared__ __align__(16) __half hsm[];
    __half (*As)[BM_][GLD_] = (__half (*)[BM_][GLD_])hsm;
    __half (*Bs)[BN_][GLD_] = (__half (*)[BN_][GLD_])(hsm + GS_ * BM_ * GLD_);

    const int tid = threadIdx.x;
    const int wid = tid >> 5;
    const int m0  = blockIdx.y * BM_;
    const int n0  = blockIdx.x * BN_;
    const int wm  = (wid & 1) * 64;     // 2 warps over 128 m
    const int wn  = (wid >> 1) * 32;    // 4 warps over 128 n

    const int lr = tid >> 2;            // 0..63
    const int lc = (tid & 3) << 3;      // 0,8,16,24

    const __half* Abase = A  + (size_t)(m0 + lr) * K + lc;
    const __half* Bbase = Bm + (size_t)(n0 + lr) * K + lc;
    const size_t rowK64 = (size_t)64 * K;

    wmma::fragment<wmma::accumulator, 16, 16, 16, float> acc[4][2];
#pragma unroll
    for (int i = 0; i < 4; i++)
#pragma unroll
        for (int j = 0; j < 2; j++)
            wmma::fill_fragment(acc[i][j], 0.0f);

    const int KT = K / GBK_;

#pragma unroll
    for (int s = 0; s < GS_ - 1; ++s) {
        const size_t ko = (size_t)s * GBK_;
        cp_async16(&As[s][lr][lc],      Abase + ko);
        cp_async16(&As[s][lr + 64][lc], Abase + ko + rowK64);
        cp_async16(&Bs[s][lr][lc],      Bbase + ko);
        cp_async16(&Bs[s][lr + 64][lc], Bbase + ko + rowK64);
        asm volatile("cp.async.commit_group;\n" ::);
    }

    for (int kt = 0; kt < KT; ++kt) {
        asm volatile("cp.async.wait_group %0;\n" :: "n"(GS_ - 2));
        __syncthreads();

        if (kt + GS_ - 1 < KT) {
            const int ws = (kt + GS_ - 1) % GS_;
            const size_t ko = (size_t)(kt + GS_ - 1) * GBK_;
            cp_async16(&As[ws][lr][lc],      Abase + ko);
            cp_async16(&As[ws][lr + 64][lc], Abase + ko + rowK64);
            cp_async16(&Bs[ws][lr][lc],      Bbase + ko);
            cp_async16(&Bs[ws][lr + 64][lc], Bbase + ko + rowK64);
        }
        asm volatile("cp.async.commit_group;\n" ::);

        const int st = kt % GS_;
#pragma unroll
        for (int ks = 0; ks < 2; ++ks) {
            wmma::fragment<wmma::matrix_a, 16, 16, 16, half, wmma::row_major> af[4];
            wmma::fragment<wmma::matrix_b, 16, 16, 16, half, wmma::col_major> bf[2];
#pragma unroll
            for (int i = 0; i < 4; i++)
                wmma::load_matrix_sync(af[i], &As[st][wm + i * 16][ks * 16], GLD_);
#pragma unroll
            for (int j = 0; j < 2; j++)
                wmma::load_matrix_sync(bf[j], &Bs[st][wn + j * 16][ks * 16], GLD_);
#pragma unroll
            for (int i = 0; i < 4; i++)
#pragma unroll
                for (int j = 0; j < 2; j++)
                    wmma::mma_sync(acc[i][j], af[i], bf[j], acc[i][j]);
        }
    }

#pragma unroll
    for (int i = 0; i < 4; i++)
#pragma unroll
        for (int j = 0; j < 2; j++)
            wmma::store_matrix_sync(
                Cm + (size_t)(m0 + wm + i * 16) * N + (n0 + wn + j * 16),
                acc[i][j], N, wmma::mem_row_major);
}

// ============================================================================
// RoPE + RMSNorm + head split; 4 heads per 256-thread block.
// ============================================================================
__global__ __launch_bounds__(256) void rope_rms(
    const float* __restrict__ qkv,
    __half* __restrict__ Qo, __half* __restrict__ Ko, __half* __restrict__ Vo)
{
    const int tid  = threadIdx.x;
    const int unit = tid >> 6;                 // 0..3
    const int i    = tid & 63;                 // pair index within head
    const int h    = blockIdx.x * 4 + unit;    // 0..23
    const int t    = blockIdx.y;
    const int b    = blockIdx.z;

    const float* src = qkv + ((size_t)(b * T_ + t)) * NQKV_ + h * DH_;
    const float x0 = src[2 * i];
    const float x1 = src[2 * i + 1];

    const bool isV = (h >= HQ_ + HKV_);

    const float inv_freq = powf(10000.0f, -(float)i * (1.0f / 64.0f));
    const float ang = (float)t * inv_freq;
    float sn, cs;
    sincosf(ang, &sn, &cs);
    const float y0 = x0 * cs - x1 * sn;
    const float y1 = x1 * cs + x0 * sn;

    float ss = y0 * y0 + y1 * y1;
#pragma unroll
    for (int off = 16; off; off >>= 1)
        ss += __shfl_xor_sync(0xffffffffu, ss, off);
    __shared__ float sh[8];
    if ((tid & 31) == 0) sh[tid >> 5] = ss;
    __syncthreads();
    float rn = rsqrtf((sh[unit * 2] + sh[unit * 2 + 1]) * (1.0f / 128.0f)
                      + 1.1920929e-07f);

    if (isV) {
        __half2* dst = (__half2*)(Vo +
            ((size_t)(b * HKV_ + (h - HQ_ - HKV_)) * T_ + t) * DH_);
        dst[i] = __floats2half2_rn(x0, x1);
    } else if (h < HQ_) {
        rn *= 0.08838834764831845f;            // fold 1/sqrt(128) into Q
        __half2* dst = (__half2*)(Qo + ((size_t)(b * HQ_ + h) * T_ + t) * DH_);
        dst[i] = __floats2half2_rn(y0 * rn, y1 * rn);
    } else {
        __half2* dst = (__half2*)(Ko + ((size_t)(b * HKV_ + (h - HQ_)) * T_ + t) * DH_);
        dst[i] = __floats2half2_rn(y0 * rn, y1 * rn);
    }
}

// ============================================================================
// Sliding-window flash attention (exact R8 structure: 64q x 64k tile),
// fp16 wmma, fp32 accumulate — now with 2 CTAs/SM (93KB smem x2 fits 228KB;
// sync stalls in one CTA hidden by the other, same lever as the R8 gemm).
// ============================================================================
#define QL_ 136             // half ld for Q/K/V tiles (128 + 8)
#define PL_ 72              // half ld for P tile (64 + 8)
#define OL_ 132             // float ld for S/O staging (128 + 4)
#define ATTN_SMEM (64 * OL_ * (int)sizeof(float) + \
                   (3 * 64 * QL_ + 64 * PL_) * (int)sizeof(__half))

__global__ __launch_bounds__(256, 2) void attn_tc(
    const __half* __restrict__ Qg, const __half* __restrict__ Kg,
    const __half* __restrict__ Vg, __half* __restrict__ Yg)
{
    extern __shared__ __align__(16) char asm_[];
    float*  Osf = (float*)asm_;                      // 64 x 132 fp32 (S & O)
    __half* Qsh = (__half*)(Osf + 64 * OL_);         // 64 x 136
    __half* Ksh = Qsh + 64 * QL_;                    // 64 x 136
    __half* Vsh = Ksh + 64 * QL_;                    // 64 x 136
    __half* Psh = Vsh + 64 * QL_;                    // 64 x 72

    const int tid = threadIdx.x;
    const int tx  = tid & 15;
    const int ty  = tid >> 4;
    const int wid = tid >> 5;
    const int q0  = blockIdx.x << 6;
    const int h   = blockIdx.y;
    const int b   = blockIdx.z;
    const int hk  = h >> 2;

    const __half* Qp = Qg + ((size_t)(b * HQ_ + h) * T_ + q0) * DH_;
    const __half* Kp = Kg + ((size_t)(b * HKV_ + hk) * T_) * DH_;
    const __half* Vp = Vg + ((size_t)(b * HKV_ + hk) * T_) * DH_;

    // Q tile: pure 16B copies (Q already scaled + fp16)
    for (int li = tid; li < 64 * 16; li += 256) {
        const int r  = li >> 4;
        const int c8 = (li & 15) << 3;
        *(uint4*)(Qsh + r * QL_ + c8) = *(const uint4*)(Qp + (size_t)r * DH_ + c8);
    }

    float m_i[4], l_i[4], acc[4][8];
#pragma unroll
    for (int i = 0; i < 4; i++) {
        m_i[i] = -1e30f; l_i[i] = 0.f;
#pragma unroll
        for (int j = 0; j < 8; j++) acc[i][j] = 0.f;
    }

    int lo = q0 - (WIN_ - 1); if (lo < 0) lo = 0;
    const int kt0 = lo >> 6;
    const int kt1 = q0 >> 6;

    for (int kt = kt0; kt <= kt1; ++kt) {
        const int k0 = kt << 6;

        // ---- load K, V tiles (16B copies) ----
        for (int li = tid; li < 64 * 16; li += 256) {
            const int r  = li >> 4;
            const int c8 = (li & 15) << 3;
            *(uint4*)(Ksh + r * QL_ + c8) =
                *(const uint4*)(Kp + (size_t)(k0 + r) * DH_ + c8);
            *(uint4*)(Vsh + r * QL_ + c8) =
                *(const uint4*)(Vp + (size_t)(k0 + r) * DH_ + c8);
        }
        __syncthreads();

        // ---- S = Q K^T: warp (wy, wx) does 32q x 16k, fp32 acc -> Osf ----
        {
            const int wy = wid & 1;
            const int wx = wid >> 1;
            wmma::fragment<wmma::accumulator, 16, 16, 16, float> sacc[2];
            wmma::fill_fragment(sacc[0], 0.0f);
            wmma::fill_fragment(sacc[1], 0.0f);
#pragma unroll
            for (int d = 0; d < DH_; d += 16) {
                wmma::fragment<wmma::matrix_a, 16, 16, 16, half, wmma::row_major> af[2];
                wmma::fragment<wmma::matrix_b, 16, 16, 16, half, wmma::col_major> bf;
                wmma::load_matrix_sync(af[0], Qsh + (wy * 32 + 0)  * QL_ + d, QL_);
                wmma::load_matrix_sync(af[1], Qsh + (wy * 32 + 16) * QL_ + d, QL_);
                wmma::load_matrix_sync(bf,    Ksh + (wx * 16) * QL_ + d, QL_);
                wmma::mma_sync(sacc[0], af[0], bf, sacc[0]);
                wmma::mma_sync(sacc[1], af[1], bf, sacc[1]);
            }
            wmma::store_matrix_sync(Osf + (wy * 32 + 0)  * OL_ + wx * 16, sacc[0], OL_, wmma::mem_row_major);
            wmma::store_matrix_sync(Osf + (wy * 32 + 16) * OL_ + wx * 16, sacc[1], OL_, wmma::mem_row_major);
        }
        __syncthreads();

        // ---- softmax (SIMT): mask, online m/l update, write fp16 P ----
#pragma unroll
        for (int i = 0; i < 4; i++) {
            const int qi = q0 + ty * 4 + i;
            const float* srow = Osf + (ty * 4 + i) * OL_ + (tx << 2);
            float s0 = srow[0], s1 = srow[1], s2 = srow[2], s3 = srow[3];
            const int kj = k0 + (tx << 2);
            s0 = (qi >= kj + 0 && (qi - kj - 0) < WIN_) ? s0 : -1e30f;
            s1 = (qi >= kj + 1 && (qi - kj - 1) < WIN_) ? s1 : -1e30f;
            s2 = (qi >= kj + 2 && (qi - kj - 2) < WIN_) ? s2 : -1e30f;
            s3 = (qi >= kj + 3 && (qi - kj - 3) < WIN_) ? s3 : -1e30f;
            float rmax = fmaxf(fmaxf(s0, s1), fmaxf(s2, s3));
#pragma unroll
            for (int off = 8; off; off >>= 1)
                rmax = fmaxf(rmax, __shfl_xor_sync(0xffffffffu, rmax, off));
            const float mn = fmaxf(m_i[i], rmax);

            float p0 = __expf(s0 - mn), p1 = __expf(s1 - mn);
            float p2 = __expf(s2 - mn), p3 = __expf(s3 - mn);
            float rs = p0 + p1 + p2 + p3;
#pragma unroll
            for (int off = 8; off; off >>= 1)
                rs += __shfl_xor_sync(0xffffffffu, rs, off);

            const float sc = __expf(m_i[i] - mn);
            l_i[i] = l_i[i] * sc + rs;
            m_i[i] = mn;
#pragma unroll
            for (int j = 0; j < 8; j++) acc[i][j] *= sc;

            __half2* prow = (__half2*)(Psh + (ty * 4 + i) * PL_ + (tx << 2));
            prow[0] = __floats2half2_rn(p0, p1);
            prow[1] = __floats2half2_rn(p2, p3);
        }
        __syncthreads();

        // ---- O_tile = P V: warp (wm, wn) does 32q x 32d -> Osf ----
        {
            const int wm = (wid & 1) * 32;
            const int wn = (wid >> 1) * 32;
            wmma::fragment<wmma::accumulator, 16, 16, 16, float> oacc[2][2];
#pragma unroll
            for (int i = 0; i < 2; i++)
#pragma unroll
                for (int j = 0; j < 2; j++)
                    wmma::fill_fragment(oacc[i][j], 0.0f);
#pragma unroll
            for (int k = 0; k < 64; k += 16) {
                wmma::fragment<wmma::matrix_a, 16, 16, 16, half, wmma::row_major> af[2];
                wmma::fragment<wmma::matrix_b, 16, 16, 16, half, wmma::row_major> bf[2];
                wmma::load_matrix_sync(af[0], Psh + (wm + 0)  * PL_ + k, PL_);
                wmma::load_matrix_sync(af[1], Psh + (wm + 16) * PL_ + k, PL_);
                wmma::load_matrix_sync(bf[0], Vsh + k * QL_ + wn + 0,  QL_);
                wmma::load_matrix_sync(bf[1], Vsh + k * QL_ + wn + 16, QL_);
#pragma unroll
                for (int i = 0; i < 2; i++)
#pragma unroll
                    for (int j = 0; j < 2; j++)
                        wmma::mma_sync(oacc[i][j], af[i], bf[j], oacc[i][j]);
            }
#pragma unroll
            for (int i = 0; i < 2; i++)
#pragma unroll
                for (int j = 0; j < 2; j++)
                    wmma::store_matrix_sync(
                        Osf + (wm + i * 16) * OL_ + wn + j * 16,
                        oacc[i][j], OL_, wmma::mem_row_major);
        }
        __syncthreads();

        // ---- merge staged O tile into SIMT accumulators ----
#pragma unroll
        for (int i = 0; i < 4; i++) {
            const float* orow = Osf + (ty * 4 + i) * OL_ + (tx << 3);
#pragma unroll
            for (int j = 0; j < 8; j++) acc[i][j] += orow[j];
        }
        __syncthreads();   // Osf/Ksh/Vsh rewritten next iteration
    }

    // epilogue: y = acc / l, fp16 (feeds the proj GEMM directly)
#pragma unroll
    for (int i = 0; i < 4; i++) {
        const float inv = 1.0f / l_i[i];
        const int t = q0 + ty * 4 + i;
        __half2 o[4];
#pragma unroll
        for (int j = 0; j < 4; j++)
            o[j] = __floats2half2_rn(acc[i][2 * j] * inv, acc[i][2 * j + 1] * inv);
        *(uint4*)(Yg + ((size_t)(b * T_ + t)) * C_ + h * DH_ + (tx << 3)) =
            *(uint4*)o;
    }
}

// ============================================================================
// launch
// ============================================================================
extern "C" void kernel_launch(void* const* d_in, const int* in_sizes, int n_in,
                              void* d_out, int out_size)
{
    const float* x      = (const float*)d_in[0];
    const float* w_qkv  = (const float*)d_in[1];
    const float* w_proj = (const float*)d_in[2];
    float* out = (float*)d_out;

    float *p_qkv;
    __half *p_Qh, *p_Kh, *p_Vh, *p_yh, *p_xh, *p_wqh, *p_wph;
    cudaGetSymbolAddress((void**)&p_qkv, g_qkv);
    cudaGetSymbolAddress((void**)&p_Qh,  g_Qh);
    cudaGetSymbolAddress((void**)&p_Kh,  g_Kh);
    cudaGetSymbolAddress((void**)&p_Vh,  g_Vh);
    cudaGetSymbolAddress((void**)&p_yh,  g_yh);
    cudaGetSymbolAddress((void**)&p_xh,  g_xh);
    cudaGetSymbolAddress((void**)&p_wqh, g_wqh);
    cudaGetSymbolAddress((void**)&p_wph, g_wph);

    cudaFuncSetAttribute(gemm_fp16, cudaFuncAttributeMaxDynamicSharedMemorySize, GEMM_SMEM);
    cudaFuncSetAttribute(attn_tc, cudaFuncAttributeMaxDynamicSharedMemorySize, ATTN_SMEM);

    // 0) convert GEMM inputs to fp16 (RNE)
    to_half<<<(MTOK_ * C_ / 4 + 255) / 256, 256>>>(x, p_xh, MTOK_ * C_ / 4);
    to_half<<<(NQKV_ * C_ / 4 + 255) / 256, 256>>>(w_qkv, p_wqh, NQKV_ * C_ / 4);
    to_half<<<(C_ * C_ / 4 + 255) / 256, 256>>>(w_proj, p_wph, C_ * C_ / 4);

    // 1) qkv = x @ w_qkv^T   (fp16 HMMA, fp32 accum, 2 CTAs/SM, BK=32)
    gemm_fp16<<<dim3(NQKV_ / BN_, MTOK_ / BM_), 256, GEMM_SMEM>>>(
        p_xh, p_wqh, p_qkv, MTOK_, NQKV_, C_);

    // 2) RoPE + RMSNorm + split; 4 heads per block
    rope_rms<<<dim3((HQ_ + 2 * HKV_) / 4, T_, B_), 256>>>(p_qkv, p_Qh, p_Kh, p_Vh);

    // 3) attention (fp16 tensor cores, 64q tiles, 2 CTAs/SM); y written fp16
    attn_tc<<<dim3(T_ / 64, HQ_, B_), 256, ATTN_SMEM>>>(p_Qh, p_Kh, p_Vh, p_yh);

    // 4) out = y @ w_proj^T  (fp16 HMMA, fp32 accum, 2 CTAs/SM, BK=32)
    gemm_fp16<<<dim3(C_ / BN_, MTOK_ / BM_), 256, GEMM_SMEM>>>(
        p_yh, p_wph, out, MTOK_, C_, C_);
}

// round 12
// speedup vs baseline: 1.1742x; 1.0275x over previous
#include <cuda_runtime.h>
#include <cstdint>
#include <math.h>
#include <mma.h>
#include <cuda_fp16.h>

using namespace nvcuda;

#define B_    2
#define T_    2048
#define C_    2048
#define HQ_   16
#define HKV_  4
#define DH_   128
#define WIN_  512
#define NQKV_ 3072          // (HQ + 2*HKV) * DH
#define MTOK_ 4096          // B * T

// ---------------- scratch (static __device__, no allocations) ----------------
__device__ __half g_Qh[B_ * HQ_ * T_ * DH_];       // fp16, pre-scaled by 1/sqrt(d)
__device__ __half g_Kh[B_ * HKV_ * T_ * DH_];
__device__ __half g_Vh[B_ * HKV_ * T_ * DH_];
__device__ __half g_yh[MTOK_ * C_];                // fp16 attention output
__device__ __half g_xh[MTOK_ * C_];                // fp16 x
__device__ __half g_wqh[NQKV_ * C_];               // fp16 w_qkv
__device__ __half g_wph[C_ * C_];                  // fp16 w_proj

// ============================================================================
// fp32 -> fp16 (RNE) conversion
// ============================================================================
__global__ __launch_bounds__(256) void to_half(
    const float* __restrict__ in, __half* __restrict__ out, int n4)
{
    const int i = blockIdx.x * blockDim.x + threadIdx.x;
    if (i >= n4) return;
    float4 v = ((const float4*)in)[i];
    __half2* o = (__half2*)out;
    o[2 * i]     = __floats2half2_rn(v.x, v.y);
    o[2 * i + 1] = __floats2half2_rn(v.z, v.w);
}

// ============================================================================
// Shared GEMM core config (proven R8/R11): CTA 128x128, BK=32, 3-stage
// cp.async, 8 warps 2(m) x 4(n), warp tile 64x32, fp32 accum, 2 CTAs/SM.
// ============================================================================
#define BM_   128
#define BN_   128
#define GBK_  32
#define GLD_  40          // halfs per row (32 + 8 pad)
#define GS_   3
#define GEMM_SMEM  (GS_ * (BM_ + BN_) * GLD_ * (int)sizeof(__half))   // 61440
#define SL_   132         // fp32 staging stride for fused epilogue
#define GEMM_QKV_SMEM (BM_ * SL_ * (int)sizeof(float))               // 67584

__device__ __forceinline__ void cp_async16(void* smem_dst, const void* gsrc) {
    unsigned int d = (unsigned int)__cvta_generic_to_shared(smem_dst);
    asm volatile("cp.async.cg.shared.global [%0], [%1], 16;\n" :: "r"(d), "l"(gsrc));
}

// mainloop shared by both GEMMs (macro-free: expressed as inline function)
template <typename EpilogueTag>
struct Tag {};

__device__ __forceinline__ void gemm_mainloop(
    const __half* __restrict__ A, const __half* __restrict__ Bm, int K,
    __half* hsm, int m0, int n0, int tid, int wid,
    wmma::fragment<wmma::accumulator, 16, 16, 16, float> (&acc)[4][2])
{
    __half (*As)[BM_][GLD_] = (__half (*)[BM_][GLD_])hsm;
    __half (*Bs)[BN_][GLD_] = (__half (*)[BN_][GLD_])(hsm + GS_ * BM_ * GLD_);

    const int wm = (wid & 1) * 64;
    const int wn = (wid >> 1) * 32;
    const int lr = tid >> 2;
    const int lc = (tid & 3) << 3;

    const __half* Abase = A  + (size_t)(m0 + lr) * K + lc;
    const __half* Bbase = Bm + (size_t)(n0 + lr) * K + lc;
    const size_t rowK64 = (size_t)64 * K;

#pragma unroll
    for (int i = 0; i < 4; i++)
#pragma unroll
        for (int j = 0; j < 2; j++)
            wmma::fill_fragment(acc[i][j], 0.0f);

    const int KT = K / GBK_;

#pragma unroll
    for (int s = 0; s < GS_ - 1; ++s) {
        const size_t ko = (size_t)s * GBK_;
        cp_async16(&As[s][lr][lc],      Abase + ko);
        cp_async16(&As[s][lr + 64][lc], Abase + ko + rowK64);
        cp_async16(&Bs[s][lr][lc],      Bbase + ko);
        cp_async16(&Bs[s][lr + 64][lc], Bbase + ko + rowK64);
        asm volatile("cp.async.commit_group;\n" ::);
    }

    for (int kt = 0; kt < KT; ++kt) {
        asm volatile("cp.async.wait_group %0;\n" :: "n"(GS_ - 2));
        __syncthreads();

        if (kt + GS_ - 1 < KT) {
            const int ws = (kt + GS_ - 1) % GS_;
            const size_t ko = (size_t)(kt + GS_ - 1) * GBK_;
            cp_async16(&As[ws][lr][lc],      Abase + ko);
            cp_async16(&As[ws][lr + 64][lc], Abase + ko + rowK64);
            cp_async16(&Bs[ws][lr][lc],      Bbase + ko);
            cp_async16(&Bs[ws][lr + 64][lc], Bbase + ko + rowK64);
        }
        asm volatile("cp.async.commit_group;\n" ::);

        const int st = kt % GS_;
#pragma unroll
        for (int ks = 0; ks < 2; ++ks) {
            wmma::fragment<wmma::matrix_a, 16, 16, 16, half, wmma::row_major> af[4];
            wmma::fragment<wmma::matrix_b, 16, 16, 16, half, wmma::col_major> bf[2];
#pragma unroll
            for (int i = 0; i < 4; i++)
                wmma::load_matrix_sync(af[i], &As[st][wm + i * 16][ks * 16], GLD_);
#pragma unroll
            for (int j = 0; j < 2; j++)
                wmma::load_matrix_sync(bf[j], &Bs[st][wn + j * 16][ks * 16], GLD_);
#pragma unroll
            for (int i = 0; i < 4; i++)
#pragma unroll
                for (int j = 0; j < 2; j++)
                    wmma::mma_sync(acc[i][j], af[i], bf[j], acc[i][j]);
        }
    }
}

// ---------------------------------------------------------------------------
// GEMM #2: plain C = A @ B^T with fp32 output (for the projection).
// ---------------------------------------------------------------------------
__global__ __launch_bounds__(256, 2) void gemm_fp16(
    const __half* __restrict__ A, const __half* __restrict__ Bm,
    float* __restrict__ Cm, int M, int N, int K)
{
    extern __shared__ __align__(16) __half hsm[];
    const int tid = threadIdx.x;
    const int wid = tid >> 5;
    const int m0  = blockIdx.y * BM_;
    const int n0  = blockIdx.x * BN_;

    wmma::fragment<wmma::accumulator, 16, 16, 16, float> acc[4][2];
    gemm_mainloop(A, Bm, K, hsm, m0, n0, tid, wid, acc);

    const int wm = (wid & 1) * 64;
    const int wn = (wid >> 1) * 32;
#pragma unroll
    for (int i = 0; i < 4; i++)
#pragma unroll
        for (int j = 0; j < 2; j++)
            wmma::store_matrix_sync(
                Cm + (size_t)(m0 + wm + i * 16) * N + (n0 + wn + j * 16),
                acc[i][j], N, wmma::mem_row_major);
}

// ---------------------------------------------------------------------------
// GEMM #1 fused: qkv = x @ w_qkv^T with RoPE + RMSNorm + head-split epilogue.
// BN=128=DH means blockIdx.x IS the head; the 128x128 tile is (128 tokens x
// one head).  Stage acc to smem fp32, 2 threads/row do RoPE + RMS + fp16
// writes straight into Q/K/V head-major layouts.  g_qkv round-trip gone.
// ---------------------------------------------------------------------------
__global__ __launch_bounds__(256, 2) void gemm_qkv(
    const __half* __restrict__ A, const __half* __restrict__ Bm,
    __half* __restrict__ Qo, __half* __restrict__ Ko, __half* __restrict__ Vo)
{
    extern __shared__ __align__(16) __half hsm[];
    __shared__ float red[256];

    const int tid = threadIdx.x;
    const int wid = tid >> 5;
    const int h   = blockIdx.x;            // 0..23: head index
    const int m0  = blockIdx.y * BM_;

    wmma::fragment<wmma::accumulator, 16, 16, 16, float> acc[4][2];
    gemm_mainloop(A, Bm, C_, hsm, m0, h * DH_, tid, wid, acc);

    // ---- stage acc tile to smem fp32 ----
    __syncthreads();                        // pipeline smem now dead
    float* stg = (float*)hsm;               // 128 x SL_
    const int wm = (wid & 1) * 64;
    const int wn = (wid >> 1) * 32;
#pragma unroll
    for (int i = 0; i < 4; i++)
#pragma unroll
        for (int j = 0; j < 2; j++)
            wmma::store_matrix_sync(stg + (wm + i * 16) * SL_ + wn + j * 16,
                                    acc[i][j], SL_, wmma::mem_row_major);
    __syncthreads();

    // ---- epilogue: 2 threads per row; thread handles 32 pairs (64 vals) ----
    const int r  = tid & 127;               // row within tile = token offset
    const int hv = tid >> 7;                // 0/1: low/high half of the head
    const int gr = m0 + r;
    const int bb = gr >> 11;                // / T_
    const int t  = gr & (T_ - 1);

    float* row = stg + r * SL_ + hv * 64;
    const bool isV = (h >= HQ_ + HKV_);

    float ss = 0.f;
    if (!isV) {
        // pass 1: rope in place, accumulate sum of squares
#pragma unroll
        for (int q = 0; q < 16; ++q) {
            float4 v = *(float4*)(row + q * 4);
            const int j0 = hv * 32 + q * 2;
            float sn0, cs0, sn1, cs1;
            sincosf((float)t * powf(10000.f, -(float)(j0)     * (1.f / 64.f)), &sn0, &cs0);
            sincosf((float)t * powf(10000.f, -(float)(j0 + 1) * (1.f / 64.f)), &sn1, &cs1);
            float4 o;
            o.x = v.x * cs0 - v.y * sn0;
            o.y = v.y * cs0 + v.x * sn0;
            o.z = v.z * cs1 - v.w * sn1;
            o.w = v.w * cs1 + v.z * sn1;
            ss += o.x * o.x + o.y * o.y + o.z * o.z + o.w * o.w;
            *(float4*)(row + q * 4) = o;
        }
    }
    red[tid] = ss;
    __syncthreads();
    float rn = rsqrtf((red[r] + red[r + 128]) * (1.0f / 128.0f) + 1.1920929e-07f);

    __half* dst;
    if (isV) {
        rn = 1.0f;
        dst = Vo + ((size_t)(bb * HKV_ + (h - HQ_ - HKV_)) * T_ + t) * DH_;
    } else if (h < HQ_) {
        rn *= 0.08838834764831845f;         // fold 1/sqrt(128) into Q
        dst = Qo + ((size_t)(bb * HQ_ + h) * T_ + t) * DH_;
    } else {
        dst = Ko + ((size_t)(bb * HKV_ + (h - HQ_)) * T_ + t) * DH_;
    }

    // pass 2: scale + convert + write fp16
#pragma unroll
    for (int q = 0; q < 8; ++q) {
        float4 a = *(float4*)(row + q * 8);
        float4 c = *(float4*)(row + q * 8 + 4);
        __half2 o[4];
        o[0] = __floats2half2_rn(a.x * rn, a.y * rn);
        o[1] = __floats2half2_rn(a.z * rn, a.w * rn);
        o[2] = __floats2half2_rn(c.x * rn, c.y * rn);
        o[3] = __floats2half2_rn(c.z * rn, c.w * rn);
        *(uint4*)(dst + hv * 64 + q * 8) = *(uint4*)o;
    }
}

// ============================================================================
// Sliding-window flash attention (exact R11: 64q x 64k, fp16 wmma, 2 CTA/SM).
// ============================================================================
#define QL_ 136
#define PL_ 72
#define OL_ 132
#define ATTN_SMEM (64 * OL_ * (int)sizeof(float) + \
                   (3 * 64 * QL_ + 64 * PL_) * (int)sizeof(__half))

__global__ __launch_bounds__(256, 2) void attn_tc(
    const __half* __restrict__ Qg, const __half* __restrict__ Kg,
    const __half* __restrict__ Vg, __half* __restrict__ Yg)
{
    extern __shared__ __align__(16) char asm_[];
    float*  Osf = (float*)asm_;
    __half* Qsh = (__half*)(Osf + 64 * OL_);
    __half* Ksh = Qsh + 64 * QL_;
    __half* Vsh = Ksh + 64 * QL_;
    __half* Psh = Vsh + 64 * QL_;

    const int tid = threadIdx.x;
    const int tx  = tid & 15;
    const int ty  = tid >> 4;
    const int wid = tid >> 5;
    const int q0  = blockIdx.x << 6;
    const int h   = blockIdx.y;
    const int b   = blockIdx.z;
    const int hk  = h >> 2;

    const __half* Qp = Qg + ((size_t)(b * HQ_ + h) * T_ + q0) * DH_;
    const __half* Kp = Kg + ((size_t)(b * HKV_ + hk) * T_) * DH_;
    const __half* Vp = Vg + ((size_t)(b * HKV_ + hk) * T_) * DH_;

    for (int li = tid; li < 64 * 16; li += 256) {
        const int r  = li >> 4;
        const int c8 = (li & 15) << 3;
        *(uint4*)(Qsh + r * QL_ + c8) = *(const uint4*)(Qp + (size_t)r * DH_ + c8);
    }

    float m_i[4], l_i[4], acc[4][8];
#pragma unroll
    for (int i = 0; i < 4; i++) {
        m_i[i] = -1e30f; l_i[i] = 0.f;
#pragma unroll
        for (int j = 0; j < 8; j++) acc[i][j] = 0.f;
    }

    int lo = q0 - (WIN_ - 1); if (lo < 0) lo = 0;
    const int kt0 = lo >> 6;
    const int kt1 = q0 >> 6;

    for (int kt = kt0; kt <= kt1; ++kt) {
        const int k0 = kt << 6;

        for (int li = tid; li < 64 * 16; li += 256) {
            const int r  = li >> 4;
            const int c8 = (li & 15) << 3;
            *(uint4*)(Ksh + r * QL_ + c8) =
                *(const uint4*)(Kp + (size_t)(k0 + r) * DH_ + c8);
            *(uint4*)(Vsh + r * QL_ + c8) =
                *(const uint4*)(Vp + (size_t)(k0 + r) * DH_ + c8);
        }
        __syncthreads();

        {
            const int wy = wid & 1;
            const int wx = wid >> 1;
            wmma::fragment<wmma::accumulator, 16, 16, 16, float> sacc[2];
            wmma::fill_fragment(sacc[0], 0.0f);
            wmma::fill_fragment(sacc[1], 0.0f);
#pragma unroll
            for (int d = 0; d < DH_; d += 16) {
                wmma::fragment<wmma::matrix_a, 16, 16, 16, half, wmma::row_major> af[2];
                wmma::fragment<wmma::matrix_b, 16, 16, 16, half, wmma::col_major> bf;
                wmma::load_matrix_sync(af[0], Qsh + (wy * 32 + 0)  * QL_ + d, QL_);
                wmma::load_matrix_sync(af[1], Qsh + (wy * 32 + 16) * QL_ + d, QL_);
                wmma::load_matrix_sync(bf,    Ksh + (wx * 16) * QL_ + d, QL_);
                wmma::mma_sync(sacc[0], af[0], bf, sacc[0]);
                wmma::mma_sync(sacc[1], af[1], bf, sacc[1]);
            }
            wmma::store_matrix_sync(Osf + (wy * 32 + 0)  * OL_ + wx * 16, sacc[0], OL_, wmma::mem_row_major);
            wmma::store_matrix_sync(Osf + (wy * 32 + 16) * OL_ + wx * 16, sacc[1], OL_, wmma::mem_row_major);
        }
        __syncthreads();

#pragma unroll
        for (int i = 0; i < 4; i++) {
            const int qi = q0 + ty * 4 + i;
            const float* srow = Osf + (ty * 4 + i) * OL_ + (tx << 2);
            float s0 = srow[0], s1 = srow[1], s2 = srow[2], s3 = srow[3];
            const int kj = k0 + (tx << 2);
            s0 = (qi >= kj + 0 && (qi - kj - 0) < WIN_) ? s0 : -1e30f;
            s1 = (qi >= kj + 1 && (qi - kj - 1) < WIN_) ? s1 : -1e30f;
            s2 = (qi >= kj + 2 && (qi - kj - 2) < WIN_) ? s2 : -1e30f;
            s3 = (qi >= kj + 3 && (qi - kj - 3) < WIN_) ? s3 : -1e30f;
            float rmax = fmaxf(fmaxf(s0, s1), fmaxf(s2, s3));
#pragma unroll
            for (int off = 8; off; off >>= 1)
                rmax = fmaxf(rmax, __shfl_xor_sync(0xffffffffu, rmax, off));
            const float mn = fmaxf(m_i[i], rmax);

            float p0 = __expf(s0 - mn), p1 = __expf(s1 - mn);
            float p2 = __expf(s2 - mn), p3 = __expf(s3 - mn);
            float rs = p0 + p1 + p2 + p3;
#pragma unroll
            for (int off = 8; off; off >>= 1)
                rs += __shfl_xor_sync(0xffffffffu, rs, off);

            const float sc = __expf(m_i[i] - mn);
            l_i[i] = l_i[i] * sc + rs;
            m_i[i] = mn;
#pragma unroll
            for (int j = 0; j < 8; j++) acc[i][j] *= sc;

            __half2* prow = (__half2*)(Psh + (ty * 4 + i) * PL_ + (tx << 2));
            prow[0] = __floats2half2_rn(p0, p1);
            prow[1] = __floats2half2_rn(p2, p3);
        }
        __syncthreads();

        {
            const int wm = (wid & 1) * 32;
            const int wn = (wid >> 1) * 32;
            wmma::fragment<wmma::accumulator, 16, 16, 16, float> oacc[2][2];
#pragma unroll
            for (int i = 0; i < 2; i++)
#pragma unroll
                for (int j = 0; j < 2; j++)
                    wmma::fill_fragment(oacc[i][j], 0.0f);
#pragma unroll
            for (int k = 0; k < 64; k += 16) {
                wmma::fragment<wmma::matrix_a, 16, 16, 16, half, wmma::row_major> af[2];
                wmma::fragment<wmma::matrix_b, 16, 16, 16, half, wmma::row_major> bf[2];
                wmma::load_matrix_sync(af[0], Psh + (wm + 0)  * PL_ + k, PL_);
                wmma::load_matrix_sync(af[1], Psh + (wm + 16) * PL_ + k, PL_);
                wmma::load_matrix_sync(bf[0], Vsh + k * QL_ + wn + 0,  QL_);
                wmma::load_matrix_sync(bf[1], Vsh + k * QL_ + wn + 16, QL_);
#pragma unroll
                for (int i = 0; i < 2; i++)
#pragma unroll
                    for (int j = 0; j < 2; j++)
                        wmma::mma_sync(oacc[i][j], af[i], bf[j], oacc[i][j]);
            }
#pragma unroll
            for (int i = 0; i < 2; i++)
#pragma unroll
                for (int j = 0; j < 2; j++)
                    wmma::store_matrix_sync(
                        Osf + (wm + i * 16) * OL_ + wn + j * 16,
                        oacc[i][j], OL_, wmma::mem_row_major);
        }
        __syncthreads();

#pragma unroll
        for (int i = 0; i < 4; i++) {
            const float* orow = Osf + (ty * 4 + i) * OL_ + (tx << 3);
#pragma unroll
            for (int j = 0; j < 8; j++) acc[i][j] += orow[j];
        }
        __syncthreads();
    }

#pragma unroll
    for (int i = 0; i < 4; i++) {
        const float inv = 1.0f / l_i[i];
        const int t = q0 + ty * 4 + i;
        __half2 o[4];
#pragma unroll
        for (int j = 0; j < 4; j++)
            o[j] = __floats2half2_rn(acc[i][2 * j] * inv, acc[i][2 * j + 1] * inv);
        *(uint4*)(Yg + ((size_t)(b * T_ + t)) * C_ + h * DH_ + (tx << 3)) =
            *(uint4*)o;
    }
}

// ============================================================================
// launch
// ============================================================================
extern "C" void kernel_launch(void* const* d_in, const int* in_sizes, int n_in,
                              void* d_out, int out_size)
{
    const float* x      = (const float*)d_in[0];
    const float* w_qkv  = (const float*)d_in[1];
    const float* w_proj = (const float*)d_in[2];
    float* out = (float*)d_out;

    __half *p_Qh, *p_Kh, *p_Vh, *p_yh, *p_xh, *p_wqh, *p_wph;
    cudaGetSymbolAddress((void**)&p_Qh,  g_Qh);
    cudaGetSymbolAddress((void**)&p_Kh,  g_Kh);
    cudaGetSymbolAddress((void**)&p_Vh,  g_Vh);
    cudaGetSymbolAddress((void**)&p_yh,  g_yh);
    cudaGetSymbolAddress((void**)&p_xh,  g_xh);
    cudaGetSymbolAddress((void**)&p_wqh, g_wqh);
    cudaGetSymbolAddress((void**)&p_wph, g_wph);

    cudaFuncSetAttribute(gemm_fp16, cudaFuncAttributeMaxDynamicSharedMemorySize, GEMM_SMEM);
    cudaFuncSetAttribute(gemm_qkv, cudaFuncAttributeMaxDynamicSharedMemorySize, GEMM_QKV_SMEM);
    cudaFuncSetAttribute(attn_tc, cudaFuncAttributeMaxDynamicSharedMemorySize, ATTN_SMEM);

    // 0) convert GEMM inputs to fp16 (RNE)
    to_half<<<(MTOK_ * C_ / 4 + 255) / 256, 256>>>(x, p_xh, MTOK_ * C_ / 4);
    to_half<<<(NQKV_ * C_ / 4 + 255) / 256, 256>>>(w_qkv, p_wqh, NQKV_ * C_ / 4);
    to_half<<<(C_ * C_ / 4 + 255) / 256, 256>>>(w_proj, p_wph, C_ * C_ / 4);

    // 1) fused: qkv GEMM + RoPE + RMSNorm + split -> fp16 Q/K/V
    gemm_qkv<<<dim3(NQKV_ / BN_, MTOK_ / BM_), 256, GEMM_QKV_SMEM>>>(
        p_xh, p_wqh, p_Qh, p_Kh, p_Vh);

    // 2) attention (fp16 tensor cores, 64q tiles, 2 CTAs/SM); y written fp16
    attn_tc<<<dim3(T_ / 64, HQ_, B_), 256, ATTN_SMEM>>>(p_Qh, p_Kh, p_Vh, p_yh);

    // 3) out = y @ w_proj^T  (fp16 HMMA, fp32 accum, 2 CTAs/SM)
    gemm_fp16<<<dim3(C_ / BN_, MTOK_ / BM_), 256, GEMM_SMEM>>>(
        p_yh, p_wph, out, MTOK_, C_, C_);
}